// round 11
// baseline (speedup 1.0000x reference)
#include <cuda_runtime.h>
#include <cuda_bf16.h>
#include <cuda_fp16.h>
#include <cstdint>
#include <math.h>

// Problem constants (fixed by the reference setup)
#define N_BATCH 2
#define LQ      16384
#define CDIM    256
#define NH      8
#define NL      4
#define NP      4
#define LIN     21760
#define NGROUP  (N_BATCH*LQ*NH)

// Scratch (device globals; allocation is forbidden)
__device__ __half g_value_h[N_BATCH*LIN*CDIM];   // fp16 projected values
__device__ float  g_off    [N_BATCH*LQ*CDIM];
__device__ float  g_attn   [N_BATCH*LQ*NH*NL*NP];// attn logits (pre-softmax)
__device__ float  g_sampled[N_BATCH*LQ*CDIM];
// Pre-transposed weights, bf16 hi/lo split: [N, K=256] row-major
__device__ __nv_bfloat16 g_wval_hi [CDIM*CDIM], g_wval_lo [CDIM*CDIM];
__device__ __nv_bfloat16 g_woff_hi [CDIM*CDIM], g_woff_lo [CDIM*CDIM];
__device__ __nv_bfloat16 g_wattn_hi[128*CDIM],  g_wattn_lo[128*CDIM];
__device__ __nv_bfloat16 g_wout_hi [CDIM*CDIM], g_wout_lo [CDIM*CDIM];

// ---------------------------------------------------------------------------
// PTX helpers (baseline PTX only — sm_103 non-variant target)
// ---------------------------------------------------------------------------
__device__ __forceinline__ uint32_t smem_u32(const void* p) {
    uint32_t a;
    asm("{ .reg .u64 t; cvta.to.shared.u64 t, %1; cvt.u32.u64 %0, t; }"
        : "=r"(a) : "l"(p));
    return a;
}
__device__ __forceinline__ void ldsm4(uint32_t* r, uint32_t addr) {
    asm volatile("ldmatrix.sync.aligned.m8n8.x4.shared.b16 {%0,%1,%2,%3}, [%4];"
                 : "=r"(r[0]), "=r"(r[1]), "=r"(r[2]), "=r"(r[3]) : "r"(addr));
}
__device__ __forceinline__ void mma16816(float* d, const uint32_t* a, const uint32_t* b) {
    asm volatile(
        "mma.sync.aligned.m16n8k16.row.col.f32.bf16.bf16.f32 "
        "{%0,%1,%2,%3}, {%4,%5,%6,%7}, {%8,%9}, {%0,%1,%2,%3};"
        : "+f"(d[0]), "+f"(d[1]), "+f"(d[2]), "+f"(d[3])
        : "r"(a[0]), "r"(a[1]), "r"(a[2]), "r"(a[3]), "r"(b[0]), "r"(b[1]));
}
#define CP_ASYNC16(dst, src) \
    asm volatile("cp.async.ca.shared.global [%0], [%1], 16;" :: "r"(dst), "l"(src))
#define CP_COMMIT()  asm volatile("cp.async.commit_group;")
#define CP_WAIT0()   asm volatile("cp.async.wait_group 0;" ::: "memory")

__device__ __forceinline__ uint32_t h2bits(float f) {
    __half2 h = __float2half2_rn(f);
    return *(uint32_t*)&h;
}

// ---------------------------------------------------------------------------
// Fused weight transpose + bf16 hi/lo split (4 weights, one launch)
// ---------------------------------------------------------------------------
__global__ void transpose_all_kernel(
    const float* __restrict__ Wv, const float* __restrict__ Wo,
    const float* __restrict__ Wa, const float* __restrict__ Wu)
{
    const int which = blockIdx.y;
    const int N = (which == 2) ? 128 : 256;
    int idx = blockIdx.x * 256 + threadIdx.x;
    if (idx >= 256 * N) return;
    const float* W = (which == 0) ? Wv : (which == 1) ? Wo : (which == 2) ? Wa : Wu;
    __nv_bfloat16* hi = (which == 0) ? g_wval_hi : (which == 1) ? g_woff_hi
                       : (which == 2) ? g_wattn_hi : g_wout_hi;
    __nv_bfloat16* lo = (which == 0) ? g_wval_lo : (which == 1) ? g_woff_lo
                       : (which == 2) ? g_wattn_lo : g_wout_lo;
    int k = idx / N, n = idx % N;
    float w = W[idx];
    __nv_bfloat16 h = __float2bfloat16(w);
    hi[n * 256 + k] = h;
    lo[n * 256 + k] = __float2bfloat16(w - __bfloat162float(h));
}

// ---------------------------------------------------------------------------
// HMMA GEMM core, bf16x3 split, double-buffered (cp.async B, reg-prefetch A).
// CTA 128x128, BK=32, 8 warps 4x2.
// ---------------------------------------------------------------------------
#define GK       256
#define GBK      32
#define ASTRIDEB 80
#define ABUF     (128 * ASTRIDEB)
#define SMEM_GEMM (8 * ABUF)           // 81920B

template<bool HALF_OUT>
__device__ __forceinline__ void gemm_core(
    const float* __restrict__ A,
    const __nv_bfloat16* __restrict__ Bt_hi,
    const __nv_bfloat16* __restrict__ Bt_lo,
    const float* __restrict__ bias,
    void* __restrict__ Cv, int ldc, int m0, int n0, char* sm)
{
    const uint32_t sb = smem_u32(sm);
    const int tid  = threadIdx.x;
    const int wid  = tid >> 5, lane = tid & 31;
    const int wm   = wid & 3,  wn   = wid >> 2;

    const int frow = tid >> 1;
    const int fkh  = (tid & 1) * 16;

    float acc[2][8][4];
    #pragma unroll
    for (int i = 0; i < 2; i++)
        #pragma unroll
        for (int j = 0; j < 8; j++)
            #pragma unroll
            for (int v = 0; v < 4; v++) acc[i][j][v] = 0.f;

    uint32_t a_addr[2];
    #pragma unroll
    for (int mt = 0; mt < 2; mt++)
        a_addr[mt] = sb + (wm * 32 + mt * 16 + (lane & 15)) * ASTRIDEB
                        + ((lane >> 4) * 8) * 2;
    uint32_t b_addr[4];
    #pragma unroll
    for (int bt = 0; bt < 4; bt++)
        b_addr[bt] = sb + (wn * 64 + bt * 16 + ((lane >> 4) * 8) + (lane & 7)) * ASTRIDEB
                        + (((lane >> 3) & 1) * 8) * 2;

    const float* arow_ptr = A + (size_t)(m0 + frow) * GK + fkh;
    const __nv_bfloat16* bh_ptr = Bt_hi + (size_t)(n0 + frow) * GK + fkh;
    const __nv_bfloat16* bl_ptr = Bt_lo + (size_t)(n0 + frow) * GK + fkh;
    const uint32_t bfill = sb + frow * ASTRIDEB + fkh * 2;

    {
        uint32_t dh = bfill + 4 * ABUF;
        uint32_t dl = dh + ABUF;
        CP_ASYNC16(dh,      bh_ptr);
        CP_ASYNC16(dh + 16, bh_ptr + 8);
        CP_ASYNC16(dl,      bl_ptr);
        CP_ASYNC16(dl + 16, bl_ptr + 8);
        CP_COMMIT();
    }
    float4 va[4];
    #pragma unroll
    for (int j = 0; j < 4; j++) va[j] = ((const float4*)arow_ptr)[j];

    for (int i = 0; i < GK / GBK; i++) {
        const int s = i & 1;
        {
            float v[16];
            #pragma unroll
            for (int j = 0; j < 4; j++) {
                v[j*4+0] = va[j].x; v[j*4+1] = va[j].y;
                v[j*4+2] = va[j].z; v[j*4+3] = va[j].w;
            }
            __nv_bfloat16 h[16], l[16];
            #pragma unroll
            for (int j = 0; j < 16; j++) {
                h[j] = __float2bfloat16(v[j]);
                l[j] = __float2bfloat16(v[j] - __bfloat162float(h[j]));
            }
            char* dh = sm + s * 2 * ABUF + frow * ASTRIDEB + fkh * 2;
            char* dl = dh + ABUF;
            ((uint4*)dh)[0] = ((uint4*)h)[0];  ((uint4*)dh)[1] = ((uint4*)h)[1];
            ((uint4*)dl)[0] = ((uint4*)l)[0];  ((uint4*)dl)[1] = ((uint4*)l)[1];
        }
        if (i < GK / GBK - 1) {
            const float4* nxt = (const float4*)(arow_ptr + (i + 1) * GBK);
            #pragma unroll
            for (int j = 0; j < 4; j++) va[j] = nxt[j];
        }

        CP_WAIT0();
        __syncthreads();

        if (i < GK / GBK - 1) {
            const __nv_bfloat16* sh = bh_ptr + (i + 1) * GBK;
            const __nv_bfloat16* sl = bl_ptr + (i + 1) * GBK;
            uint32_t dh = bfill + 4 * ABUF + (s ^ 1) * 2 * ABUF;
            uint32_t dl = dh + ABUF;
            CP_ASYNC16(dh,      sh);
            CP_ASYNC16(dh + 16, sh + 8);
            CP_ASYNC16(dl,      sl);
            CP_ASYNC16(dl + 16, sl + 8);
            CP_COMMIT();
        }

        const uint32_t aoffS = s * 2 * ABUF;
        const uint32_t boffS = 4 * ABUF + s * 2 * ABUF;
        #pragma unroll
        for (int kk = 0; kk < GBK; kk += 16) {
            const uint32_t ko = kk * 2;
            uint32_t ah[2][4], al[2][4];
            #pragma unroll
            for (int mt = 0; mt < 2; mt++) {
                ldsm4(ah[mt], a_addr[mt] + aoffS + ko);
                ldsm4(al[mt], a_addr[mt] + aoffS + ABUF + ko);
            }
            #pragma unroll
            for (int bt = 0; bt < 4; bt++) {
                uint32_t bh[4], bl[4];
                ldsm4(bh, b_addr[bt] + boffS + ko);
                ldsm4(bl, b_addr[bt] + boffS + ABUF + ko);
                #pragma unroll
                for (int mt = 0; mt < 2; mt++) {
                    float* d0 = acc[mt][bt * 2 + 0];
                    float* d1 = acc[mt][bt * 2 + 1];
                    mma16816(d0, ah[mt], bh + 0);
                    mma16816(d0, ah[mt], bl + 0);
                    mma16816(d0, al[mt], bh + 0);
                    mma16816(d1, ah[mt], bh + 2);
                    mma16816(d1, ah[mt], bl + 2);
                    mma16816(d1, al[mt], bh + 2);
                }
            }
        }
        __syncthreads();
    }

    const int r_in = lane >> 2;
    const int c_in = (lane & 3) * 2;
    #pragma unroll
    for (int mt = 0; mt < 2; mt++) {
        const int rbase = m0 + wm * 32 + mt * 16 + r_in;
        #pragma unroll
        for (int nf = 0; nf < 8; nf++) {
            const int col = n0 + wn * 64 + nf * 8 + c_in;
            const float b0 = bias[col], b1 = bias[col + 1];
            float* d = acc[mt][nf];
            if (HALF_OUT) {
                __half* C = (__half*)Cv;
                *(__half2*)(C + (size_t)rbase       * ldc + col) =
                    __floats2half2_rn(d[0] + b0, d[1] + b1);
                *(__half2*)(C + (size_t)(rbase + 8) * ldc + col) =
                    __floats2half2_rn(d[2] + b0, d[3] + b1);
            } else {
                float* C = (float*)Cv;
                *(float2*)(C + (size_t)rbase       * ldc + col) = make_float2(d[0] + b0, d[1] + b1);
                *(float2*)(C + (size_t)(rbase + 8) * ldc + col) = make_float2(d[2] + b0, d[3] + b1);
            }
        }
    }
}

// Merged independent projections: value (fp16 out) + offset + attn.
// 1-D grid, segments: [0,680) val (340x2), [680,1192) off (256x2), [1192,1448) attn.
#define VAL_BLKS  (2 * ((N_BATCH * LIN) / 128))   // 680
#define OFF_BLKS  (2 * ((N_BATCH * LQ) / 128))    // 512
#define ATTN_BLKS ((N_BATCH * LQ) / 128)          // 256
#define ALL_BLKS  (VAL_BLKS + OFF_BLKS + ATTN_BLKS)

__global__ __launch_bounds__(256, 2) void gemm_all_kernel(
    const float* __restrict__ input_flatten,
    const float* __restrict__ query,
    const float* __restrict__ b_val,
    const float* __restrict__ b_off,
    const float* __restrict__ b_attn)
{
    extern __shared__ __align__(16) char sm[];
    const int b = blockIdx.x;
    if (b < VAL_BLKS) {
        const int bx = b % ((N_BATCH * LIN) / 128), by = b / ((N_BATCH * LIN) / 128);
        gemm_core<true>(input_flatten, g_wval_hi, g_wval_lo, b_val,
                        g_value_h, 256, bx * 128, by * 128, sm);
    } else if (b < VAL_BLKS + OFF_BLKS) {
        const int bb = b - VAL_BLKS;
        const int bx = bb & 255, by = bb >> 8;
        gemm_core<false>(query, g_woff_hi, g_woff_lo, b_off,
                         g_off, 256, bx * 128, by * 128, sm);
    } else {
        const int bx = b - (VAL_BLKS + OFF_BLKS);
        gemm_core<false>(query, g_wattn_hi, g_wattn_lo, b_attn,
                         g_attn, 128, bx * 128, 0, sm);
    }
}

// Output projection (depends on sampler)
__global__ __launch_bounds__(256, 2) void gemm_out_kernel(
    const float* __restrict__ bias, float* __restrict__ C)
{
    extern __shared__ __align__(16) char sm[];
    gemm_core<false>(g_sampled, g_wout_hi, g_wout_lo, bias, C, 256,
                     blockIdx.x * 128, blockIdx.y * 128, sm);
}

// ---------------------------------------------------------------------------
// Fused sampler v3: warp = (n, q) — ALL 8 heads. Geometry+softmax once per
// (head, point) across lanes (4 items/lane), weights pre-packed as half2;
// gather uses LDG.128 (8 channels/lane, 4 lanes/head) + HFMA2 corner math
// with fp32 cross-point accumulation.
//
// Weight pairing: sample at (l,p) weighted by softmax'd attn[p*4+l]
// (the reference pairs p-major sampled values with l-major weights).
// ---------------------------------------------------------------------------
__global__ __launch_bounds__(256) void fused_sample_kernel()
{
    // [warp][pi*8 + m]: per pi, 8 consecutive 16B entries = 128B across all
    // banks; each entry broadcast to 4 lanes. Conflict-free.
    __shared__ __align__(16) int4  sidx[8 * 128];
    __shared__ __align__(16) uint4 swp [8 * 128];   // packed half2 weights

    const int tid  = threadIdx.x;
    const int wid  = tid >> 5, lane = tid & 31;
    const int row_q = blockIdx.x * 8 + wid;     // n*LQ + q
    const int q    = row_q & (LQ - 1);
    const int n    = row_q >> 14;

    const float refx = ((q & 127) + 0.5f) * (1.0f / 128.0f);
    const float refy = ((q >> 7)  + 0.5f) * (1.0f / 128.0f);

    // ---- geometry phase: 4 items/lane; item = (m, pi)
    const int pi = lane & 15;
    const int l  = pi >> 2, p = pi & 3;
    const int W  = 128 >> l;
    const int start = (l == 0) ? 0 : (l == 1) ? 16384 : (l == 2) ? 20480 : 21504;

    #pragma unroll
    for (int it = 0; it < 4; it++) {
        const int m = (lane >> 4) * 4 + it;     // lanes 0-15: heads 0-3; 16-31: 4-7

        const float2 off2 = *(const float2*)(g_off + (size_t)row_q * CDIM + m * 32 + 2 * pi);
        float lg = g_attn[((size_t)row_q * NH + m) * 16 + p * 4 + l]; // transposed (l,p)

        // softmax over this head's 16 lanes
        float mx = lg;
        #pragma unroll
        for (int k = 8; k >= 1; k >>= 1)
            mx = fmaxf(mx, __shfl_xor_sync(0xffffffffu, mx, k, 16));
        float e = expf(lg - mx);
        float s = e;
        #pragma unroll
        for (int k = 8; k >= 1; k >>= 1)
            s += __shfl_xor_sync(0xffffffffu, s, k, 16);
        const float aw = e / s;

        const float x = refx * (float)W + off2.x - 0.5f;
        const float y = refy * (float)W + off2.y - 0.5f;
        const float xf = floorf(x), yf = floorf(y);
        const int x0 = (int)xf, y0 = (int)yf;
        const float wx1 = x - xf, wy1 = y - yf;
        const float wx0 = 1.f - wx1, wy0 = 1.f - wy1;

        const bool vx0 = (x0 >= 0) && (x0 < W);
        const bool vx1 = (x0 >= -1) && (x0 < W - 1);
        const bool vy0 = (y0 >= 0) && (y0 < W);
        const bool vy1 = (y0 >= -1) && (y0 < W - 1);

        const int xc0 = min(max(x0, 0), W - 1);
        const int xc1 = min(max(x0 + 1, 0), W - 1);
        const int yc0 = min(max(y0, 0), W - 1);
        const int yc1 = min(max(y0 + 1, 0), W - 1);

        // byte offsets of value rows (512B/row); head folded in at gather
        const int rb = (n * LIN + start);
        int4 idx;
        idx.x = (rb + yc0 * W + xc0) * 512;
        idx.y = (rb + yc0 * W + xc1) * 512;
        idx.z = (rb + yc1 * W + xc0) * 512;
        idx.w = (rb + yc1 * W + xc1) * 512;
        uint4 wp;
        wp.x = h2bits((vy0 && vx0) ? aw * wy0 * wx0 : 0.f);
        wp.y = h2bits((vy0 && vx1) ? aw * wy0 * wx1 : 0.f);
        wp.z = h2bits((vy1 && vx0) ? aw * wy1 * wx0 : 0.f);
        wp.w = h2bits((vy1 && vx1) ? aw * wy1 * wx1 : 0.f);

        sidx[wid * 128 + pi * 8 + m] = idx;
        swp [wid * 128 + pi * 8 + m] = wp;
    }
    __syncwarp();

    // ---- gather phase: head hh = lane>>2, lane quarter l4 = lane&3 covers
    // channels hh*32 + l4*8 .. +7 (16 bytes, LDG.128)
    const int hh = lane >> 2;
    const int l4 = lane & 3;
    const char* vb = (const char*)g_value_h + hh * 64 + l4 * 16;

    float2 acc0 = make_float2(0.f, 0.f), acc1 = make_float2(0.f, 0.f);
    float2 acc2 = make_float2(0.f, 0.f), acc3 = make_float2(0.f, 0.f);
    #pragma unroll
    for (int pp = 0; pp < 16; pp++) {
        const int4  idx = sidx[wid * 128 + pp * 8 + hh];
        const uint4 wp  = swp [wid * 128 + pp * 8 + hh];
        uint4 v0 = *(const uint4*)(vb + idx.x);
        uint4 v1 = *(const uint4*)(vb + idx.y);
        uint4 v2 = *(const uint4*)(vb + idx.z);
        uint4 v3 = *(const uint4*)(vb + idx.w);
        const __half2 h00 = *(const __half2*)&wp.x;
        const __half2 h01 = *(const __half2*)&wp.y;
        const __half2 h10 = *(const __half2*)&wp.z;
        const __half2 h11 = *(const __half2*)&wp.w;

        __half2 s0 = __hmul2(h00, *(__half2*)&v0.x);
        s0 = __hfma2(h01, *(__half2*)&v1.x, s0);
        s0 = __hfma2(h10, *(__half2*)&v2.x, s0);
        s0 = __hfma2(h11, *(__half2*)&v3.x, s0);
        __half2 s1 = __hmul2(h00, *(__half2*)&v0.y);
        s1 = __hfma2(h01, *(__half2*)&v1.y, s1);
        s1 = __hfma2(h10, *(__half2*)&v2.y, s1);
        s1 = __hfma2(h11, *(__half2*)&v3.y, s1);
        __half2 s2 = __hmul2(h00, *(__half2*)&v0.z);
        s2 = __hfma2(h01, *(__half2*)&v1.z, s2);
        s2 = __hfma2(h10, *(__half2*)&v2.z, s2);
        s2 = __hfma2(h11, *(__half2*)&v3.z, s2);
        __half2 s3 = __hmul2(h00, *(__half2*)&v0.w);
        s3 = __hfma2(h01, *(__half2*)&v1.w, s3);
        s3 = __hfma2(h10, *(__half2*)&v2.w, s3);
        s3 = __hfma2(h11, *(__half2*)&v3.w, s3);

        float2 f0 = __half22float2(s0), f1 = __half22float2(s1);
        float2 f2 = __half22float2(s2), f3 = __half22float2(s3);
        acc0.x += f0.x; acc0.y += f0.y;
        acc1.x += f1.x; acc1.y += f1.y;
        acc2.x += f2.x; acc2.y += f2.y;
        acc3.x += f3.x; acc3.y += f3.y;
    }
    float* dst = g_sampled + (size_t)row_q * CDIM + hh * 32 + l4 * 8;
    *(float4*)(dst + 0) = make_float4(acc0.x, acc0.y, acc1.x, acc1.y);
    *(float4*)(dst + 4) = make_float4(acc2.x, acc2.y, acc3.x, acc3.y);
}

// ---------------------------------------------------------------------------
// kernel_launch
// ---------------------------------------------------------------------------
extern "C" void kernel_launch(void* const* d_in, const int* in_sizes, int n_in,
                              void* d_out, int out_size)
{
    const float* query         = (const float*)d_in[0];
    const float* input_flatten = (const float*)d_in[2];
    const float* W_off  = (const float*)d_in[5];
    const float* b_off  = (const float*)d_in[6];
    const float* W_attn = (const float*)d_in[7];
    const float* b_attn = (const float*)d_in[8];
    const float* W_val  = (const float*)d_in[9];
    const float* b_val  = (const float*)d_in[10];
    const float* W_out  = (const float*)d_in[11];
    const float* b_out  = (const float*)d_in[12];
    float* out = (float*)d_out;

    cudaFuncSetAttribute(gemm_all_kernel,
                         cudaFuncAttributeMaxDynamicSharedMemorySize, SMEM_GEMM);
    cudaFuncSetAttribute(gemm_out_kernel,
                         cudaFuncAttributeMaxDynamicSharedMemorySize, SMEM_GEMM);

    // 0) weight transpose + split (single launch)
    transpose_all_kernel<<<dim3(256, 4), 256>>>(W_val, W_off, W_attn, W_out);

    // 1) all independent projections in one launch (value->fp16, off, attn)
    gemm_all_kernel<<<ALL_BLKS, 256, SMEM_GEMM>>>(
        input_flatten, query, b_val, b_off, b_attn);

    // 2) fused softmax + geometry + sampling (8 heads/warp, LDG.128)
    fused_sample_kernel<<<(N_BATCH * LQ) / 8, 256>>>();

    // 3) output projection [32768, 256]
    gemm_out_kernel<<<dim3((N_BATCH * LQ) / 128, 2), 256, SMEM_GEMM>>>(b_out, out);
}

// round 13
// speedup vs baseline: 1.1995x; 1.1995x over previous
#include <cuda_runtime.h>
#include <cuda_bf16.h>
#include <cuda_fp16.h>
#include <cstdint>
#include <math.h>

// Problem constants (fixed by the reference setup)
#define N_BATCH 2
#define LQ      16384
#define CDIM    256
#define NH      8
#define NL      4
#define NP      4
#define LIN     21760
#define NGROUP  (N_BATCH*LQ*NH)

// Scratch (device globals; allocation is forbidden)
__device__ __half g_value_h  [N_BATCH*LIN*CDIM]; // fp16 projected values
__device__ float  g_off      [N_BATCH*LQ*CDIM];
__device__ float  g_attn     [N_BATCH*LQ*NH*NL*NP];
__device__ __half g_sampled_h[N_BATCH*LQ*CDIM];  // fp16 sampled output
// Pre-transposed weights, fp16 hi/lo split: [N, K=256] row-major
__device__ __half g_wval_hi [CDIM*CDIM], g_wval_lo [CDIM*CDIM];
__device__ __half g_woff_hi [CDIM*CDIM], g_woff_lo [CDIM*CDIM];
__device__ __half g_wattn_hi[128*CDIM],  g_wattn_lo[128*CDIM];
__device__ __half g_wout_hi [CDIM*CDIM], g_wout_lo [CDIM*CDIM];

// ---------------------------------------------------------------------------
// PTX helpers (baseline PTX only — sm_103 non-variant target)
// ---------------------------------------------------------------------------
__device__ __forceinline__ uint32_t smem_u32(const void* p) {
    uint32_t a;
    asm("{ .reg .u64 t; cvta.to.shared.u64 t, %1; cvt.u32.u64 %0, t; }"
        : "=r"(a) : "l"(p));
    return a;
}
__device__ __forceinline__ void ldsm4(uint32_t* r, uint32_t addr) {
    asm volatile("ldmatrix.sync.aligned.m8n8.x4.shared.b16 {%0,%1,%2,%3}, [%4];"
                 : "=r"(r[0]), "=r"(r[1]), "=r"(r[2]), "=r"(r[3]) : "r"(addr));
}
// fp16 MMA, fp32 accumulate
__device__ __forceinline__ void mma16816h(float* d, const uint32_t* a, const uint32_t* b) {
    asm volatile(
        "mma.sync.aligned.m16n8k16.row.col.f32.f16.f16.f32 "
        "{%0,%1,%2,%3}, {%4,%5,%6,%7}, {%8,%9}, {%0,%1,%2,%3};"
        : "+f"(d[0]), "+f"(d[1]), "+f"(d[2]), "+f"(d[3])
        : "r"(a[0]), "r"(a[1]), "r"(a[2]), "r"(a[3]), "r"(b[0]), "r"(b[1]));
}
#define CP_ASYNC16(dst, src) \
    asm volatile("cp.async.ca.shared.global [%0], [%1], 16;" :: "r"(dst), "l"(src))
#define CP_COMMIT()  asm volatile("cp.async.commit_group;")
#define CP_WAIT0()   asm volatile("cp.async.wait_group 0;" ::: "memory")

// ---------------------------------------------------------------------------
// Fused weight transpose + fp16 hi/lo split (4 weights, one launch)
// ---------------------------------------------------------------------------
__global__ void transpose_all_kernel(
    const float* __restrict__ Wv, const float* __restrict__ Wo,
    const float* __restrict__ Wa, const float* __restrict__ Wu)
{
    const int which = blockIdx.y;
    const int N = (which == 2) ? 128 : 256;
    int idx = blockIdx.x * 256 + threadIdx.x;
    if (idx >= 256 * N) return;
    const float* W = (which == 0) ? Wv : (which == 1) ? Wo : (which == 2) ? Wa : Wu;
    __half* hi = (which == 0) ? g_wval_hi : (which == 1) ? g_woff_hi
                : (which == 2) ? g_wattn_hi : g_wout_hi;
    __half* lo = (which == 0) ? g_wval_lo : (which == 1) ? g_woff_lo
                : (which == 2) ? g_wattn_lo : g_wout_lo;
    int k = idx / N, n = idx % N;
    float w = W[idx];
    __half h = __float2half_rn(w);
    hi[n * 256 + k] = h;
    lo[n * 256 + k] = __float2half_rn(w - __half2float(h));
}

// ---------------------------------------------------------------------------
// HMMA GEMM core, fp16 with variable term count:
//   TERMS=1: C = Ah*Bh            (A fp32 -> fp16 hi only)
//   TERMS=2: C = A*(Bh+Bl)        (A already fp16 in global, cp.async'd)
//   TERMS=3: C = Ah*Bh+Ah*Bl+Al*Bh (A fp32 -> fp16 hi/lo split)
// CTA 128x128, BK=32, 8 warps 4x2, double-buffered.
// ---------------------------------------------------------------------------
#define GK       256
#define GBK      32
#define ASTRIDEB 80
#define ABUF     (128 * ASTRIDEB)
#define SMEM_GEMM (8 * ABUF)           // 81920B

template<int TERMS, bool A_FP16, bool HALF_OUT>
__device__ __forceinline__ void gemm_core(
    const void* __restrict__ Av,
    const __half* __restrict__ Bt_hi,
    const __half* __restrict__ Bt_lo,
    const float* __restrict__ bias,
    void* __restrict__ Cv, int ldc, int m0, int n0, char* sm)
{
    const uint32_t sb = smem_u32(sm);
    const int tid  = threadIdx.x;
    const int wid  = tid >> 5, lane = tid & 31;
    const int wm   = wid & 3,  wn   = wid >> 2;

    const int frow = tid >> 1;
    const int fkh  = (tid & 1) * 16;

    float acc[2][8][4];
    #pragma unroll
    for (int i = 0; i < 2; i++)
        #pragma unroll
        for (int j = 0; j < 8; j++)
            #pragma unroll
            for (int v = 0; v < 4; v++) acc[i][j][v] = 0.f;

    uint32_t a_addr[2];
    #pragma unroll
    for (int mt = 0; mt < 2; mt++)
        a_addr[mt] = sb + (wm * 32 + mt * 16 + (lane & 15)) * ASTRIDEB
                        + ((lane >> 4) * 8) * 2;
    uint32_t b_addr[4];
    #pragma unroll
    for (int bt = 0; bt < 4; bt++)
        b_addr[bt] = sb + (wn * 64 + bt * 16 + ((lane >> 4) * 8) + (lane & 7)) * ASTRIDEB
                        + (((lane >> 3) & 1) * 8) * 2;

    const __half* bh_ptr = Bt_hi + (size_t)(n0 + frow) * GK + fkh;
    const __half* bl_ptr = (TERMS >= 2) ? (Bt_lo + (size_t)(n0 + frow) * GK + fkh) : nullptr;
    const float*  af_ptr = A_FP16 ? nullptr : ((const float*)Av + (size_t)(m0 + frow) * GK + fkh);
    const __half* ah_ptr = A_FP16 ? ((const __half*)Av + (size_t)(m0 + frow) * GK + fkh) : nullptr;
    const uint32_t bfill = sb + frow * ASTRIDEB + fkh * 2;

    // prologue: stage 0
    {
        uint32_t dBh = bfill + 4 * ABUF;
        CP_ASYNC16(dBh,      bh_ptr);
        CP_ASYNC16(dBh + 16, bh_ptr + 8);
        if (TERMS >= 2) {
            uint32_t dBl = dBh + ABUF;
            CP_ASYNC16(dBl,      bl_ptr);
            CP_ASYNC16(dBl + 16, bl_ptr + 8);
        }
        if (A_FP16) {
            CP_ASYNC16(bfill,      ah_ptr);
            CP_ASYNC16(bfill + 16, ah_ptr + 8);
        }
        CP_COMMIT();
    }
    float4 va[4];
    if (!A_FP16) {
        #pragma unroll
        for (int j = 0; j < 4; j++) va[j] = ((const float4*)af_ptr)[j];
    }

    for (int i = 0; i < GK / GBK; i++) {
        const int s = i & 1;
        if (!A_FP16) {
            float v[16];
            #pragma unroll
            for (int j = 0; j < 4; j++) {
                v[j*4+0] = va[j].x; v[j*4+1] = va[j].y;
                v[j*4+2] = va[j].z; v[j*4+3] = va[j].w;
            }
            __half h[16], l[16];
            #pragma unroll
            for (int j = 0; j < 16; j++) {
                h[j] = __float2half_rn(v[j]);
                if (TERMS == 3) l[j] = __float2half_rn(v[j] - __half2float(h[j]));
            }
            char* dh = sm + s * 2 * ABUF + frow * ASTRIDEB + fkh * 2;
            ((uint4*)dh)[0] = ((uint4*)h)[0];  ((uint4*)dh)[1] = ((uint4*)h)[1];
            if (TERMS == 3) {
                char* dl = dh + ABUF;
                ((uint4*)dl)[0] = ((uint4*)l)[0];  ((uint4*)dl)[1] = ((uint4*)l)[1];
            }
            if (i < GK / GBK - 1) {
                const float4* nxt = (const float4*)(af_ptr + (i + 1) * GBK);
                #pragma unroll
                for (int j = 0; j < 4; j++) va[j] = nxt[j];
            }
        }

        CP_WAIT0();
        __syncthreads();

        if (i < GK / GBK - 1) {
            uint32_t dBh = bfill + 4 * ABUF + (s ^ 1) * 2 * ABUF;
            const __half* sh = bh_ptr + (i + 1) * GBK;
            CP_ASYNC16(dBh,      sh);
            CP_ASYNC16(dBh + 16, sh + 8);
            if (TERMS >= 2) {
                uint32_t dBl = dBh + ABUF;
                const __half* sl = bl_ptr + (i + 1) * GBK;
                CP_ASYNC16(dBl,      sl);
                CP_ASYNC16(dBl + 16, sl + 8);
            }
            if (A_FP16) {
                uint32_t dA = bfill + (s ^ 1) * 2 * ABUF;
                const __half* sa = ah_ptr + (i + 1) * GBK;
                CP_ASYNC16(dA,      sa);
                CP_ASYNC16(dA + 16, sa + 8);
            }
            CP_COMMIT();
        }

        const uint32_t aoffS = s * 2 * ABUF;
        const uint32_t boffS = 4 * ABUF + s * 2 * ABUF;
        #pragma unroll
        for (int kk = 0; kk < GBK; kk += 16) {
            const uint32_t ko = kk * 2;
            uint32_t ah[2][4], al[2][4];
            #pragma unroll
            for (int mt = 0; mt < 2; mt++) {
                ldsm4(ah[mt], a_addr[mt] + aoffS + ko);
                if (TERMS == 3) ldsm4(al[mt], a_addr[mt] + aoffS + ABUF + ko);
            }
            #pragma unroll
            for (int bt = 0; bt < 4; bt++) {
                uint32_t bh[4], bl[4];
                ldsm4(bh, b_addr[bt] + boffS + ko);
                if (TERMS >= 2) ldsm4(bl, b_addr[bt] + boffS + ABUF + ko);
                #pragma unroll
                for (int mt = 0; mt < 2; mt++) {
                    float* d0 = acc[mt][bt * 2 + 0];
                    float* d1 = acc[mt][bt * 2 + 1];
                    mma16816h(d0, ah[mt], bh + 0);
                    if (TERMS >= 2) mma16816h(d0, ah[mt], bl + 0);
                    if (TERMS == 3) mma16816h(d0, al[mt], bh + 0);
                    mma16816h(d1, ah[mt], bh + 2);
                    if (TERMS >= 2) mma16816h(d1, ah[mt], bl + 2);
                    if (TERMS == 3) mma16816h(d1, al[mt], bh + 2);
                }
            }
        }
        __syncthreads();
    }

    const int r_in = lane >> 2;
    const int c_in = (lane & 3) * 2;
    #pragma unroll
    for (int mt = 0; mt < 2; mt++) {
        const int rbase = m0 + wm * 32 + mt * 16 + r_in;
        #pragma unroll
        for (int nf = 0; nf < 8; nf++) {
            const int col = n0 + wn * 64 + nf * 8 + c_in;
            const float b0 = bias[col], b1 = bias[col + 1];
            float* d = acc[mt][nf];
            if (HALF_OUT) {
                __half* C = (__half*)Cv;
                *(__half2*)(C + (size_t)rbase       * ldc + col) =
                    __floats2half2_rn(d[0] + b0, d[1] + b1);
                *(__half2*)(C + (size_t)(rbase + 8) * ldc + col) =
                    __floats2half2_rn(d[2] + b0, d[3] + b1);
            } else {
                float* C = (float*)Cv;
                *(float2*)(C + (size_t)rbase       * ldc + col) = make_float2(d[0] + b0, d[1] + b1);
                *(float2*)(C + (size_t)(rbase + 8) * ldc + col) = make_float2(d[2] + b0, d[3] + b1);
            }
        }
    }
}

// Value projection: fp16 3-term, fp32 A, fp16 out
__global__ __launch_bounds__(256, 2) void gemm_val_kernel(
    const float* __restrict__ A, const float* __restrict__ bias)
{
    extern __shared__ __align__(16) char sm[];
    gemm_core<3, false, true>(A, g_wval_hi, g_wval_lo, bias,
                              g_value_h, 256, blockIdx.x * 128, blockIdx.y * 128, sm);
}

// Merged offset + attn projections: 1-term fp16 (grid.y 0,1 -> off; 2 -> attn)
__global__ __launch_bounds__(256, 2) void gemm_q_kernel(
    const float* __restrict__ query,
    const float* __restrict__ b_off, const float* __restrict__ b_attn)
{
    extern __shared__ __align__(16) char sm[];
    if (blockIdx.y < 2) {
        gemm_core<1, false, false>(query, g_woff_hi, nullptr, b_off,
                                   g_off, 256, blockIdx.x * 128, blockIdx.y * 128, sm);
    } else {
        gemm_core<1, false, false>(query, g_wattn_hi, nullptr, b_attn,
                                   g_attn, 128, blockIdx.x * 128, 0, sm);
    }
}

// Output projection: 2-term fp16, A already fp16 (g_sampled_h)
__global__ __launch_bounds__(256, 2) void gemm_out_kernel(
    const float* __restrict__ bias, float* __restrict__ C)
{
    extern __shared__ __align__(16) char sm[];
    gemm_core<2, true, false>(g_sampled_h, g_wout_hi, g_wout_lo, bias,
                              C, 256, blockIdx.x * 128, blockIdx.y * 128, sm);
}

// ---------------------------------------------------------------------------
// Fused sampler (R10 v2, verbatim except fp16 output): warp = (n,q,head-quad),
// geometry+softmax once per (head,point) across lanes, smem exchange, LDG.64
// gather + HFMA2 corner weighting, fp32 cross-point accumulation.
//
// Weight pairing: sample at (l,p) weighted by softmax'd attn[p*4+l]
// (the reference pairs p-major sampled values with l-major weights).
// ---------------------------------------------------------------------------
__global__ __launch_bounds__(256) void fused_sample_kernel()
{
    __shared__ __align__(16) int4   sidx[8 * 64];
    __shared__ __align__(16) float4 sw  [8 * 64];

    const int tid  = threadIdx.x;
    const int wid  = tid >> 5, lane = tid & 31;
    const int wg   = blockIdx.x * 8 + wid;      // (n, q, hq)
    const int hq   = wg & 1;
    const int q    = (wg >> 1) & (LQ - 1);
    const int n    = wg >> 15;
    const int row_q = n * LQ + q;

    const float refx = ((q & 127) + 0.5f) * (1.0f / 128.0f);
    const float refy = ((q >> 7)  + 0.5f) * (1.0f / 128.0f);

    #pragma unroll
    for (int it = 0; it < 2; it++) {
        const int hh = (lane >> 4) + it * 2;
        const int pi = lane & 15;
        const int m  = hq * 4 + hh;
        const int l  = pi >> 2, p = pi & 3;

        const float2 off2 = *(const float2*)(g_off + (size_t)row_q * CDIM + m * 32 + 2 * pi);
        float lg = g_attn[((size_t)row_q * NH + m) * 16 + p * 4 + l]; // transposed (l,p)

        float mx = lg;
        #pragma unroll
        for (int k = 8; k >= 1; k >>= 1)
            mx = fmaxf(mx, __shfl_xor_sync(0xffffffffu, mx, k, 16));
        float e = expf(lg - mx);
        float s = e;
        #pragma unroll
        for (int k = 8; k >= 1; k >>= 1)
            s += __shfl_xor_sync(0xffffffffu, s, k, 16);
        const float aw = e / s;

        const int W = 128 >> l;
        const int start = (l == 0) ? 0 : (l == 1) ? 16384 : (l == 2) ? 20480 : 21504;

        const float x = refx * (float)W + off2.x - 0.5f;
        const float y = refy * (float)W + off2.y - 0.5f;
        const float xf = floorf(x), yf = floorf(y);
        const int x0 = (int)xf, y0 = (int)yf;
        const float wx1 = x - xf, wy1 = y - yf;
        const float wx0 = 1.f - wx1, wy0 = 1.f - wy1;

        const bool vx0 = (x0 >= 0) && (x0 < W);
        const bool vx1 = (x0 >= -1) && (x0 < W - 1);
        const bool vy0 = (y0 >= 0) && (y0 < W);
        const bool vy1 = (y0 >= -1) && (y0 < W - 1);

        const int xc0 = min(max(x0, 0), W - 1);
        const int xc1 = min(max(x0 + 1, 0), W - 1);
        const int yc0 = min(max(y0, 0), W - 1);
        const int yc1 = min(max(y0 + 1, 0), W - 1);

        const int rb = (n * LIN + start);
        int4 idx;
        idx.x = (rb + yc0 * W + xc0) * 512;
        idx.y = (rb + yc0 * W + xc1) * 512;
        idx.z = (rb + yc1 * W + xc0) * 512;
        idx.w = (rb + yc1 * W + xc1) * 512;
        float4 w;
        w.x = (vy0 && vx0) ? aw * wy0 * wx0 : 0.f;
        w.y = (vy0 && vx1) ? aw * wy0 * wx1 : 0.f;
        w.z = (vy1 && vx0) ? aw * wy1 * wx0 : 0.f;
        w.w = (vy1 && vx1) ? aw * wy1 * wx1 : 0.f;

        sidx[wid * 64 + pi * 4 + hh] = idx;
        sw  [wid * 64 + pi * 4 + hh] = w;
    }
    __syncwarp();

    const int hh = lane >> 3;
    const int d4 = lane & 7;
    const int m  = hq * 4 + hh;
    const char* vb = (const char*)g_value_h + m * 64 + d4 * 8;

    float2 accA = make_float2(0.f, 0.f);
    float2 accB = make_float2(0.f, 0.f);
    #pragma unroll
    for (int pi = 0; pi < 16; pi++) {
        const int4   idx = sidx[wid * 64 + pi * 4 + hh];
        const float4 w   = sw  [wid * 64 + pi * 4 + hh];
        uint2 v0 = *(const uint2*)(vb + idx.x);
        uint2 v1 = *(const uint2*)(vb + idx.y);
        uint2 v2 = *(const uint2*)(vb + idx.z);
        uint2 v3 = *(const uint2*)(vb + idx.w);
        const __half2 h00 = __float2half2_rn(w.x);
        const __half2 h01 = __float2half2_rn(w.y);
        const __half2 h10 = __float2half2_rn(w.z);
        const __half2 h11 = __float2half2_rn(w.w);

        __half2 pa = __hmul2(h00, *(__half2*)&v0.x);
        pa = __hfma2(h01, *(__half2*)&v1.x, pa);
        pa = __hfma2(h10, *(__half2*)&v2.x, pa);
        pa = __hfma2(h11, *(__half2*)&v3.x, pa);
        __half2 pb = __hmul2(h00, *(__half2*)&v0.y);
        pb = __hfma2(h01, *(__half2*)&v1.y, pb);
        pb = __hfma2(h10, *(__half2*)&v2.y, pb);
        pb = __hfma2(h11, *(__half2*)&v3.y, pb);

        float2 fa = __half22float2(pa);
        float2 fb = __half22float2(pb);
        accA.x += fa.x; accA.y += fa.y;
        accB.x += fb.x; accB.y += fb.y;
    }
    // store fp16 (4 channels, 8 bytes)
    __half2 o0 = __floats2half2_rn(accA.x, accA.y);
    __half2 o1 = __floats2half2_rn(accB.x, accB.y);
    uint2 o;
    o.x = *(uint32_t*)&o0;
    o.y = *(uint32_t*)&o1;
    *(uint2*)(g_sampled_h + (size_t)row_q * CDIM + m * 32 + d4 * 4) = o;
}

// ---------------------------------------------------------------------------
// kernel_launch
// ---------------------------------------------------------------------------
extern "C" void kernel_launch(void* const* d_in, const int* in_sizes, int n_in,
                              void* d_out, int out_size)
{
    const float* query         = (const float*)d_in[0];
    const float* input_flatten = (const float*)d_in[2];
    const float* W_off  = (const float*)d_in[5];
    const float* b_off  = (const float*)d_in[6];
    const float* W_attn = (const float*)d_in[7];
    const float* b_attn = (const float*)d_in[8];
    const float* W_val  = (const float*)d_in[9];
    const float* b_val  = (const float*)d_in[10];
    const float* W_out  = (const float*)d_in[11];
    const float* b_out  = (const float*)d_in[12];
    float* out = (float*)d_out;

    cudaFuncSetAttribute(gemm_val_kernel,
                         cudaFuncAttributeMaxDynamicSharedMemorySize, SMEM_GEMM);
    cudaFuncSetAttribute(gemm_q_kernel,
                         cudaFuncAttributeMaxDynamicSharedMemorySize, SMEM_GEMM);
    cudaFuncSetAttribute(gemm_out_kernel,
                         cudaFuncAttributeMaxDynamicSharedMemorySize, SMEM_GEMM);

    // 0) weight transpose + fp16 split (single launch)
    transpose_all_kernel<<<dim3(256, 4), 256>>>(W_val, W_off, W_attn, W_out);

    // 1) value projection [43520, 256] -> fp16 (3-term fp16)
    gemm_val_kernel<<<dim3((N_BATCH * LIN) / 128, 2), 256, SMEM_GEMM>>>(
        input_flatten, b_val);

    // 2) merged offset + attn projections (1-term fp16)
    gemm_q_kernel<<<dim3((N_BATCH * LQ) / 128, 3), 256, SMEM_GEMM>>>(
        query, b_off, b_attn);

    // 3) fused softmax + geometry + sampling (4 heads/warp, LDG.64) -> fp16
    fused_sample_kernel<<<(N_BATCH * LQ * 2) / 8, 256>>>();

    // 4) output projection [32768, 256] (2-term fp16, fp16 A)
    gemm_out_kernel<<<dim3((N_BATCH * LQ) / 128, 2), 256, SMEM_GEMM>>>(b_out, out);
}

// round 17
// speedup vs baseline: 1.2813x; 1.0683x over previous
#include <cuda_runtime.h>
#include <cuda_bf16.h>
#include <cuda_fp16.h>
#include <cstdint>
#include <math.h>

// Problem constants (fixed by the reference setup)
#define N_BATCH 2
#define LQ      16384
#define CDIM    256
#define NH      8
#define NL      4
#define NP      4
#define LIN     21760
#define NGROUP  (N_BATCH*LQ*NH)

// Scratch (device globals; allocation is forbidden)
__device__ __half g_value_h  [N_BATCH*LIN*CDIM]; // fp16 projected values
__device__ float  g_off      [N_BATCH*LQ*CDIM];
__device__ float  g_attn     [N_BATCH*LQ*NH*NL*NP];
__device__ __half g_sampled_h[N_BATCH*LQ*CDIM];  // fp16 sampled output
// Pre-transposed weights, fp16 hi/lo split: [N, K=256] row-major
__device__ __half g_wval_hi [CDIM*CDIM], g_wval_lo [CDIM*CDIM];
__device__ __half g_woff_hi [CDIM*CDIM], g_woff_lo [CDIM*CDIM];
__device__ __half g_wattn_hi[128*CDIM],  g_wattn_lo[128*CDIM];
__device__ __half g_wout_hi [CDIM*CDIM], g_wout_lo [CDIM*CDIM];

// ---------------------------------------------------------------------------
// PTX helpers (baseline PTX only — sm_103 non-variant target)
// ---------------------------------------------------------------------------
__device__ __forceinline__ uint32_t smem_u32(const void* p) {
    uint32_t a;
    asm("{ .reg .u64 t; cvta.to.shared.u64 t, %1; cvt.u32.u64 %0, t; }"
        : "=r"(a) : "l"(p));
    return a;
}
__device__ __forceinline__ void ldsm4(uint32_t* r, uint32_t addr) {
    asm volatile("ldmatrix.sync.aligned.m8n8.x4.shared.b16 {%0,%1,%2,%3}, [%4];"
                 : "=r"(r[0]), "=r"(r[1]), "=r"(r[2]), "=r"(r[3]) : "r"(addr));
}
// fp16 MMA, fp32 accumulate
__device__ __forceinline__ void mma16816h(float* d, const uint32_t* a, const uint32_t* b) {
    asm volatile(
        "mma.sync.aligned.m16n8k16.row.col.f32.f16.f16.f32 "
        "{%0,%1,%2,%3}, {%4,%5,%6,%7}, {%8,%9}, {%0,%1,%2,%3};"
        : "+f"(d[0]), "+f"(d[1]), "+f"(d[2]), "+f"(d[3])
        : "r"(a[0]), "r"(a[1]), "r"(a[2]), "r"(a[3]), "r"(b[0]), "r"(b[1]));
}
#define CP_ASYNC16(dst, src) \
    asm volatile("cp.async.ca.shared.global [%0], [%1], 16;" :: "r"(dst), "l"(src))
#define CP_COMMIT()  asm volatile("cp.async.commit_group;")
#define CP_WAIT0()   asm volatile("cp.async.wait_group 0;" ::: "memory")

// ---------------------------------------------------------------------------
// Fused weight transpose + fp16 hi/lo split (4 weights, one launch)
// ---------------------------------------------------------------------------
__global__ void transpose_all_kernel(
    const float* __restrict__ Wv, const float* __restrict__ Wo,
    const float* __restrict__ Wa, const float* __restrict__ Wu)
{
    const int which = blockIdx.y;
    const int N = (which == 2) ? 128 : 256;
    int idx = blockIdx.x * 256 + threadIdx.x;
    if (idx >= 256 * N) return;
    const float* W = (which == 0) ? Wv : (which == 1) ? Wo : (which == 2) ? Wa : Wu;
    __half* hi = (which == 0) ? g_wval_hi : (which == 1) ? g_woff_hi
                : (which == 2) ? g_wattn_hi : g_wout_hi;
    __half* lo = (which == 0) ? g_wval_lo : (which == 1) ? g_woff_lo
                : (which == 2) ? g_wattn_lo : g_wout_lo;
    int k = idx / N, n = idx % N;
    float w = W[idx];
    __half h = __float2half_rn(w);
    hi[n * 256 + k] = h;
    lo[n * 256 + k] = __float2half_rn(w - __half2float(h));
}

// ---------------------------------------------------------------------------
// HMMA GEMM core, fp16 with variable term count:
//   TERMS=1: C = Ah*Bh            (A fp32 -> fp16 hi only)
//   TERMS=2, A_FP16=false: C = Ah*(Bh+Bl)
//   TERMS=2, A_FP16=true:  C = A*(Bh+Bl)   (A fp16 in global, cp.async'd)
//   TERMS=3: C = Ah*Bh+Ah*Bl+Al*Bh
// CTA 128x128, BK=32, 8 warps 4x2, double-buffered.
// ---------------------------------------------------------------------------
#define GK       256
#define GBK      32
#define ASTRIDEB 80
#define ABUF     (128 * ASTRIDEB)
#define SMEM_GEMM (8 * ABUF)           // 81920B

template<int TERMS, bool A_FP16, bool HALF_OUT>
__device__ __forceinline__ void gemm_core(
    const void* __restrict__ Av,
    const __half* __restrict__ Bt_hi,
    const __half* __restrict__ Bt_lo,
    const float* __restrict__ bias,
    void* __restrict__ Cv, int ldc, int m0, int n0, char* sm)
{
    const uint32_t sb = smem_u32(sm);
    const int tid  = threadIdx.x;
    const int wid  = tid >> 5, lane = tid & 31;
    const int wm   = wid & 3,  wn   = wid >> 2;

    const int frow = tid >> 1;
    const int fkh  = (tid & 1) * 16;

    float acc[2][8][4];
    #pragma unroll
    for (int i = 0; i < 2; i++)
        #pragma unroll
        for (int j = 0; j < 8; j++)
            #pragma unroll
            for (int v = 0; v < 4; v++) acc[i][j][v] = 0.f;

    uint32_t a_addr[2];
    #pragma unroll
    for (int mt = 0; mt < 2; mt++)
        a_addr[mt] = sb + (wm * 32 + mt * 16 + (lane & 15)) * ASTRIDEB
                        + ((lane >> 4) * 8) * 2;
    uint32_t b_addr[4];
    #pragma unroll
    for (int bt = 0; bt < 4; bt++)
        b_addr[bt] = sb + (wn * 64 + bt * 16 + ((lane >> 4) * 8) + (lane & 7)) * ASTRIDEB
                        + (((lane >> 3) & 1) * 8) * 2;

    const __half* bh_ptr = Bt_hi + (size_t)(n0 + frow) * GK + fkh;
    const __half* bl_ptr = (TERMS >= 2) ? (Bt_lo + (size_t)(n0 + frow) * GK + fkh) : nullptr;
    const float*  af_ptr = A_FP16 ? nullptr : ((const float*)Av + (size_t)(m0 + frow) * GK + fkh);
    const __half* ah_ptr = A_FP16 ? ((const __half*)Av + (size_t)(m0 + frow) * GK + fkh) : nullptr;
    const uint32_t bfill = sb + frow * ASTRIDEB + fkh * 2;

    // prologue: stage 0
    {
        uint32_t dBh = bfill + 4 * ABUF;
        CP_ASYNC16(dBh,      bh_ptr);
        CP_ASYNC16(dBh + 16, bh_ptr + 8);
        if (TERMS >= 2) {
            uint32_t dBl = dBh + ABUF;
            CP_ASYNC16(dBl,      bl_ptr);
            CP_ASYNC16(dBl + 16, bl_ptr + 8);
        }
        if (A_FP16) {
            CP_ASYNC16(bfill,      ah_ptr);
            CP_ASYNC16(bfill + 16, ah_ptr + 8);
        }
        CP_COMMIT();
    }
    float4 va[4];
    if (!A_FP16) {
        #pragma unroll
        for (int j = 0; j < 4; j++) va[j] = ((const float4*)af_ptr)[j];
    }

    for (int i = 0; i < GK / GBK; i++) {
        const int s = i & 1;
        if (!A_FP16) {
            float v[16];
            #pragma unroll
            for (int j = 0; j < 4; j++) {
                v[j*4+0] = va[j].x; v[j*4+1] = va[j].y;
                v[j*4+2] = va[j].z; v[j*4+3] = va[j].w;
            }
            __half h[16], l[16];
            #pragma unroll
            for (int j = 0; j < 16; j++) {
                h[j] = __float2half_rn(v[j]);
                if (TERMS == 3) l[j] = __float2half_rn(v[j] - __half2float(h[j]));
            }
            char* dh = sm + s * 2 * ABUF + frow * ASTRIDEB + fkh * 2;
            ((uint4*)dh)[0] = ((uint4*)h)[0];  ((uint4*)dh)[1] = ((uint4*)h)[1];
            if (TERMS == 3) {
                char* dl = dh + ABUF;
                ((uint4*)dl)[0] = ((uint4*)l)[0];  ((uint4*)dl)[1] = ((uint4*)l)[1];
            }
            if (i < GK / GBK - 1) {
                const float4* nxt = (const float4*)(af_ptr + (i + 1) * GBK);
                #pragma unroll
                for (int j = 0; j < 4; j++) va[j] = nxt[j];
            }
        }

        CP_WAIT0();
        __syncthreads();

        if (i < GK / GBK - 1) {
            uint32_t dBh = bfill + 4 * ABUF + (s ^ 1) * 2 * ABUF;
            const __half* sh = bh_ptr + (i + 1) * GBK;
            CP_ASYNC16(dBh,      sh);
            CP_ASYNC16(dBh + 16, sh + 8);
            if (TERMS >= 2) {
                uint32_t dBl = dBh + ABUF;
                const __half* sl = bl_ptr + (i + 1) * GBK;
                CP_ASYNC16(dBl,      sl);
                CP_ASYNC16(dBl + 16, sl + 8);
            }
            if (A_FP16) {
                uint32_t dA = bfill + (s ^ 1) * 2 * ABUF;
                const __half* sa = ah_ptr + (i + 1) * GBK;
                CP_ASYNC16(dA,      sa);
                CP_ASYNC16(dA + 16, sa + 8);
            }
            CP_COMMIT();
        }

        const uint32_t aoffS = s * 2 * ABUF;
        const uint32_t boffS = 4 * ABUF + s * 2 * ABUF;
        #pragma unroll
        for (int kk = 0; kk < GBK; kk += 16) {
            const uint32_t ko = kk * 2;
            uint32_t ah[2][4], al[2][4];
            #pragma unroll
            for (int mt = 0; mt < 2; mt++) {
                ldsm4(ah[mt], a_addr[mt] + aoffS + ko);
                if (TERMS == 3) ldsm4(al[mt], a_addr[mt] + aoffS + ABUF + ko);
            }
            #pragma unroll
            for (int bt = 0; bt < 4; bt++) {
                uint32_t bh[4], bl[4];
                ldsm4(bh, b_addr[bt] + boffS + ko);
                if (TERMS >= 2) ldsm4(bl, b_addr[bt] + boffS + ABUF + ko);
                #pragma unroll
                for (int mt = 0; mt < 2; mt++) {
                    float* d0 = acc[mt][bt * 2 + 0];
                    float* d1 = acc[mt][bt * 2 + 1];
                    mma16816h(d0, ah[mt], bh + 0);
                    if (TERMS >= 2) mma16816h(d0, ah[mt], bl + 0);
                    if (TERMS == 3) mma16816h(d0, al[mt], bh + 0);
                    mma16816h(d1, ah[mt], bh + 2);
                    if (TERMS >= 2) mma16816h(d1, ah[mt], bl + 2);
                    if (TERMS == 3) mma16816h(d1, al[mt], bh + 2);
                }
            }
        }
        __syncthreads();
    }

    const int r_in = lane >> 2;
    const int c_in = (lane & 3) * 2;
    #pragma unroll
    for (int mt = 0; mt < 2; mt++) {
        const int rbase = m0 + wm * 32 + mt * 16 + r_in;
        #pragma unroll
        for (int nf = 0; nf < 8; nf++) {
            const int col = n0 + wn * 64 + nf * 8 + c_in;
            const float b0 = bias[col], b1 = bias[col + 1];
            float* d = acc[mt][nf];
            if (HALF_OUT) {
                __half* C = (__half*)Cv;
                *(__half2*)(C + (size_t)rbase       * ldc + col) =
                    __floats2half2_rn(d[0] + b0, d[1] + b1);
                *(__half2*)(C + (size_t)(rbase + 8) * ldc + col) =
                    __floats2half2_rn(d[2] + b0, d[3] + b1);
            } else {
                float* C = (float*)Cv;
                *(float2*)(C + (size_t)rbase       * ldc + col) = make_float2(d[0] + b0, d[1] + b1);
                *(float2*)(C + (size_t)(rbase + 8) * ldc + col) = make_float2(d[2] + b0, d[3] + b1);
            }
        }
    }
}

// Merged independent projections, 1-D grid:
//   [0, VAL_BLKS)            value proj: 2-term, fp32 A, fp16 out
//   [VAL_BLKS, +OFF_BLKS)    offset proj: 1-term
//   [.., +ATTN_BLKS)         attn proj:   1-term
#define VAL_X     ((N_BATCH * LIN) / 128)         // 340
#define VAL_BLKS  (2 * VAL_X)                     // 680
#define OFF_X     ((N_BATCH * LQ) / 128)          // 256
#define OFF_BLKS  (2 * OFF_X)                     // 512
#define ATTN_BLKS OFF_X                           // 256
#define ALL_BLKS  (VAL_BLKS + OFF_BLKS + ATTN_BLKS)  // 1448

__global__ __launch_bounds__(256, 2) void gemm_all_kernel(
    const float* __restrict__ input_flatten,
    const float* __restrict__ query,
    const float* __restrict__ b_val,
    const float* __restrict__ b_off,
    const float* __restrict__ b_attn)
{
    extern __shared__ __align__(16) char sm[];
    const int b = blockIdx.x;
    if (b < VAL_BLKS) {
        const int bx = b % VAL_X, by = b / VAL_X;
        gemm_core<2, false, true>(input_flatten, g_wval_hi, g_wval_lo, b_val,
                                  g_value_h, 256, bx * 128, by * 128, sm);
    } else if (b < VAL_BLKS + OFF_BLKS) {
        const int bb = b - VAL_BLKS;
        const int bx = bb % OFF_X, by = bb / OFF_X;
        gemm_core<1, false, false>(query, g_woff_hi, nullptr, b_off,
                                   g_off, 256, bx * 128, by * 128, sm);
    } else {
        const int bx = b - (VAL_BLKS + OFF_BLKS);
        gemm_core<1, false, false>(query, g_wattn_hi, nullptr, b_attn,
                                   g_attn, 128, bx * 128, 0, sm);
    }
}

// Output projection: 2-term fp16, A already fp16 (g_sampled_h)
__global__ __launch_bounds__(256, 2) void gemm_out_kernel(
    const float* __restrict__ bias, float* __restrict__ C)
{
    extern __shared__ __align__(16) char sm[];
    gemm_core<2, true, false>(g_sampled_h, g_wout_hi, g_wout_lo, bias,
                              C, 256, blockIdx.x * 128, blockIdx.y * 128, sm);
}

// ---------------------------------------------------------------------------
// Fused sampler (R10 v2 + fp16 output): warp = (n,q,head-quad),
// geometry+softmax once per (head,point) across lanes, smem exchange, LDG.64
// gather + HFMA2 corner weighting, fp32 cross-point accumulation.
//
// Weight pairing: sample at (l,p) weighted by softmax'd attn[p*4+l]
// (the reference pairs p-major sampled values with l-major weights).
// ---------------------------------------------------------------------------
__global__ __launch_bounds__(256) void fused_sample_kernel()
{
    __shared__ __align__(16) int4   sidx[8 * 64];
    __shared__ __align__(16) float4 sw  [8 * 64];

    const int tid  = threadIdx.x;
    const int wid  = tid >> 5, lane = tid & 31;
    const int wg   = blockIdx.x * 8 + wid;      // (n, q, hq)
    const int hq   = wg & 1;
    const int q    = (wg >> 1) & (LQ - 1);
    const int n    = wg >> 15;
    const int row_q = n * LQ + q;

    const float refx = ((q & 127) + 0.5f) * (1.0f / 128.0f);
    const float refy = ((q >> 7)  + 0.5f) * (1.0f / 128.0f);

    #pragma unroll
    for (int it = 0; it < 2; it++) {
        const int hh = (lane >> 4) + it * 2;
        const int pi = lane & 15;
        const int m  = hq * 4 + hh;
        const int l  = pi >> 2, p = pi & 3;

        const float2 off2 = *(const float2*)(g_off + (size_t)row_q * CDIM + m * 32 + 2 * pi);
        float lg = g_attn[((size_t)row_q * NH + m) * 16 + p * 4 + l]; // transposed (l,p)

        float mx = lg;
        #pragma unroll
        for (int k = 8; k >= 1; k >>= 1)
            mx = fmaxf(mx, __shfl_xor_sync(0xffffffffu, mx, k, 16));
        float e = expf(lg - mx);
        float s = e;
        #pragma unroll
        for (int k = 8; k >= 1; k >>= 1)
            s += __shfl_xor_sync(0xffffffffu, s, k, 16);
        const float aw = e / s;

        const int W = 128 >> l;
        const int start = (l == 0) ? 0 : (l == 1) ? 16384 : (l == 2) ? 20480 : 21504;

        const float x = refx * (float)W + off2.x - 0.5f;
        const float y = refy * (float)W + off2.y - 0.5f;
        const float xf = floorf(x), yf = floorf(y);
        const int x0 = (int)xf, y0 = (int)yf;
        const float wx1 = x - xf, wy1 = y - yf;
        const float wx0 = 1.f - wx1, wy0 = 1.f - wy1;

        const bool vx0 = (x0 >= 0) && (x0 < W);
        const bool vx1 = (x0 >= -1) && (x0 < W - 1);
        const bool vy0 = (y0 >= 0) && (y0 < W);
        const bool vy1 = (y0 >= -1) && (y0 < W - 1);

        const int xc0 = min(max(x0, 0), W - 1);
        const int xc1 = min(max(x0 + 1, 0), W - 1);
        const int yc0 = min(max(y0, 0), W - 1);
        const int yc1 = min(max(y0 + 1, 0), W - 1);

        const int rb = (n * LIN + start);
        int4 idx;
        idx.x = (rb + yc0 * W + xc0) * 512;
        idx.y = (rb + yc0 * W + xc1) * 512;
        idx.z = (rb + yc1 * W + xc0) * 512;
        idx.w = (rb + yc1 * W + xc1) * 512;
        float4 w;
        w.x = (vy0 && vx0) ? aw * wy0 * wx0 : 0.f;
        w.y = (vy0 && vx1) ? aw * wy0 * wx1 : 0.f;
        w.z = (vy1 && vx0) ? aw * wy1 * wx0 : 0.f;
        w.w = (vy1 && vx1) ? aw * wy1 * wx1 : 0.f;

        sidx[wid * 64 + pi * 4 + hh] = idx;
        sw  [wid * 64 + pi * 4 + hh] = w;
    }
    __syncwarp();

    const int hh = lane >> 3;
    const int d4 = lane & 7;
    const int m  = hq * 4 + hh;
    const char* vb = (const char*)g_value_h + m * 64 + d4 * 8;

    float2 accA = make_float2(0.f, 0.f);
    float2 accB = make_float2(0.f, 0.f);
    #pragma unroll
    for (int pi = 0; pi < 16; pi++) {
        const int4   idx = sidx[wid * 64 + pi * 4 + hh];
        const float4 w   = sw  [wid * 64 + pi * 4 + hh];
        uint2 v0 = *(const uint2*)(vb + idx.x);
        uint2 v1 = *(const uint2*)(vb + idx.y);
        uint2 v2 = *(const uint2*)(vb + idx.z);
        uint2 v3 = *(const uint2*)(vb + idx.w);
        const __half2 h00 = __float2half2_rn(w.x);
        const __half2 h01 = __float2half2_rn(w.y);
        const __half2 h10 = __float2half2_rn(w.z);
        const __half2 h11 = __float2half2_rn(w.w);

        __half2 pa = __hmul2(h00, *(__half2*)&v0.x);
        pa = __hfma2(h01, *(__half2*)&v1.x, pa);
        pa = __hfma2(h10, *(__half2*)&v2.x, pa);
        pa = __hfma2(h11, *(__half2*)&v3.x, pa);
        __half2 pb = __hmul2(h00, *(__half2*)&v0.y);
        pb = __hfma2(h01, *(__half2*)&v1.y, pb);
        pb = __hfma2(h10, *(__half2*)&v2.y, pb);
        pb = __hfma2(h11, *(__half2*)&v3.y, pb);

        float2 fa = __half22float2(pa);
        float2 fb = __half22float2(pb);
        accA.x += fa.x; accA.y += fa.y;
        accB.x += fb.x; accB.y += fb.y;
    }
    __half2 o0 = __floats2half2_rn(accA.x, accA.y);
    __half2 o1 = __floats2half2_rn(accB.x, accB.y);
    uint2 o;
    o.x = *(uint32_t*)&o0;
    o.y = *(uint32_t*)&o1;
    *(uint2*)(g_sampled_h + (size_t)row_q * CDIM + m * 32 + d4 * 4) = o;
}

// ---------------------------------------------------------------------------
// kernel_launch
// ---------------------------------------------------------------------------
extern "C" void kernel_launch(void* const* d_in, const int* in_sizes, int n_in,
                              void* d_out, int out_size)
{
    const float* query         = (const float*)d_in[0];
    const float* input_flatten = (const float*)d_in[2];
    const float* W_off  = (const float*)d_in[5];
    const float* b_off  = (const float*)d_in[6];
    const float* W_attn = (const float*)d_in[7];
    const float* b_attn = (const float*)d_in[8];
    const float* W_val  = (const float*)d_in[9];
    const float* b_val  = (const float*)d_in[10];
    const float* W_out  = (const float*)d_in[11];
    const float* b_out  = (const float*)d_in[12];
    float* out = (float*)d_out;

    cudaFuncSetAttribute(gemm_all_kernel,
                         cudaFuncAttributeMaxDynamicSharedMemorySize, SMEM_GEMM);
    cudaFuncSetAttribute(gemm_out_kernel,
                         cudaFuncAttributeMaxDynamicSharedMemorySize, SMEM_GEMM);

    // 0) weight transpose + fp16 split (single launch)
    transpose_all_kernel<<<dim3(256, 4), 256>>>(W_val, W_off, W_attn, W_out);

    // 1) all independent projections in one launch
    //    (value 2-term -> fp16; offset 1-term; attn 1-term)
    gemm_all_kernel<<<ALL_BLKS, 256, SMEM_GEMM>>>(
        input_flatten, query, b_val, b_off, b_attn);

    // 2) fused softmax + geometry + sampling (4 heads/warp, LDG.64) -> fp16
    fused_sample_kernel<<<(N_BATCH * LQ * 2) / 8, 256>>>();

    // 3) output projection [32768, 256] (2-term fp16, fp16 A)
    gemm_out_kernel<<<dim3((N_BATCH * LQ) / 128, 2), 256, SMEM_GEMM>>>(b_out, out);
}